// round 13
// baseline (speedup 1.0000x reference)
#include <cuda_runtime.h>
#include <cstdint>

#define R_   4
#define B_   512
#define T_   150
#define HD   32
#define K_   600
#define NK   160            // per-(r,b) correction-list capacity
#define X0   0.55f          // poly validity radius
#define T3c  (-0.33333333333f)
#define T5c  (0.13333333333f)
#define T7c  (-0.05396825397f)

// device intermediates
__device__ float g_attf[B_ * K_];
__device__ float g_G[R_ * B_ * 128];          // [q*128 + j*32 + c], q=r*512+b, j in {1,3,5,7}
__device__ float g_w1t[K_ * 128];             // W1 transposed [k][c]
__device__ int   g_klist[R_ * B_ * NK];
__device__ int   g_kn[R_ * B_];

// ---------------- helpers ----------------
__device__ __forceinline__ float tanha(float x) {
    float y; asm("tanh.approx.f32 %0, %1;" : "=f"(y) : "f"(x)); return y;
}
__device__ __forceinline__ unsigned long long pk2(float lo, float hi) {
    unsigned long long r;
    asm("mov.b64 %0, {%1, %2};" : "=l"(r) : "f"(lo), "f"(hi)); return r;
}
__device__ __forceinline__ void fma2(unsigned long long &acc,
                                     unsigned long long u, unsigned long long w) {
    asm("fma.rn.f32x2 %0, %1, %2, %0;" : "+l"(acc) : "l"(u), "l"(w));
}
__device__ __forceinline__ float2 up2(unsigned long long v) {
    float lo, hi;
    asm("mov.b64 {%0, %1}, %2;" : "=f"(lo), "=f"(hi) : "l"(v));
    return make_float2(lo, hi);
}

// ---------------- kernel G: grid (37,4) = 148 CTAs, one wave (r12, measured 18.7us) ----------------
#define G_SMEM 116400

__global__ __launch_bounds__(512, 1)
void camG(const float* __restrict__ feats,
          const float* __restrict__ a,
          const float* __restrict__ Wc,
          const float* __restrict__ W1)
{
    extern __shared__ float sm[];
    const int tid = threadIdx.x;
    const int r   = blockIdx.y;
    const int bx  = blockIdx.x;

    if (bx >= 32) {
        if (bx == 36) {
            for (int i = tid; i < 32 * K_; i += 512) {
                int c_l = i / K_;
                int k   = i - c_l * K_;
                g_w1t[k * 128 + r * 32 + c_l] = __ldg(W1 + (r * 32 + c_l) * K_ + k);
            }
            return;
        }
        const int p = bx - 32;
        const int w = tid >> 5, lane = tid & 31;
        const float ar = fabsf(__ldg(a + r));
        #pragma unroll 1
        for (int i = 0; i < 8; i++) {
            const int b = p * 16 + w + 64 * i;
            float m = 0.f;
            #pragma unroll
            for (int it = 0; it < 5; it++) {
                int t = it * 32 + lane;
                if (t < T_) m = fmaxf(m, fabsf(__ldg(feats + (r * B_ + b) * T_ + t)));
            }
            #pragma unroll
            for (int off = 16; off; off >>= 1)
                m = fmaxf(m, __shfl_xor_sync(0xffffffffu, m, off));
            const float xmax = ar * m;
            float gk[19];
            #pragma unroll
            for (int it = 0; it < 19; it++) {
                int k = it * 32 + lane;
                gk[it] = (k < K_) ? __ldg(feats + b * K_ + k) : 0.f;
            }
            int base = 0;
            #pragma unroll
            for (int it = 0; it < 19; it++) {
                int k = it * 32 + lane;
                bool pq = (k < K_) && (fabsf(gk[it]) * xmax > X0);
                unsigned mask = __ballot_sync(0xffffffffu, pq);
                int pre = __popc(mask & ((1u << lane) - 1u));
                if (pq && (base + pre) < NK)
                    g_klist[(r * B_ + b) * NK + base + pre] = k;
                base += __popc(mask);
            }
            if (lane == 0) g_kn[r * B_ + b] = base;
        }
        return;
    }

    float*  wcT = sm;                          // [300][33]
    float4* gp  = (float4*)(sm + 300 * 33);    // [16][300]
    const int b0  = bx * 16;
    const int b_l = tid >> 5;
    const int c   = tid & 31;

    unsigned long long A01 = 0ull, A23 = 0ull;

    for (int kc = 0; kc < K_; kc += 300) {
        __syncthreads();
        for (int i = tid; i < 32 * 300; i += 512) {
            int cc = i / 300, kk = i - cc * 300;
            wcT[kk * 33 + cc] = __ldg(Wc + (r * HD + cc) * K_ + kc + kk);
        }
        for (int i = tid; i < 16 * 300; i += 512) {
            int bb = i / 300, kk = i - bb * 300;
            float g  = __ldg(feats + (b0 + bb) * K_ + kc + kk);
            float g2 = g * g;
            float g3 = g * g2, g5 = g3 * g2, g7 = g5 * g2;
            gp[bb * 300 + kk] = make_float4(g, g3, g5, g7);
        }
        __syncthreads();
        #pragma unroll 4
        for (int kk = 0; kk < 300; kk++) {
            ulonglong2 gv = ((const ulonglong2*)gp)[b_l * 300 + kk];
            float wc = wcT[kk * 33 + c];
            unsigned long long wc2 = pk2(wc, wc);
            fma2(A01, gv.x, wc2);
            fma2(A23, gv.y, wc2);
        }
    }
    float2 s01 = up2(A01), s23 = up2(A23);
    int base = ((r * B_) + b0 + b_l) * 128 + c;
    g_G[base]      = s01.x;
    g_G[base + 32] = s01.y;
    g_G[base + 64] = s23.x;
    g_G[base + 96] = s23.y;
}

// ---------------- kernel H: warp-per-(r,b), lane-per-c, G in registers ----------------
// grid 256, block 256 (8 warps = 8 q-blocks per CTA; 2048 warps total)
__global__ __launch_bounds__(256, 2)
void camH(const float* __restrict__ feats,
          const float* __restrict__ a,
          const float* __restrict__ W,
          const float* __restrict__ Wc,
          const float* __restrict__ Wh)
{
    __shared__ float f_s[8][160];
    __shared__ float gl_s[8][NK];
    __shared__ int   ki_s[8][NK];

    const int tid  = threadIdx.x;
    const int w    = tid >> 5;
    const int lane = tid & 31;
    const int q    = blockIdx.x * 8 + w;    // 0..2047
    const int r    = q >> 9;
    const int b    = q & 511;

    // warp-private staging
    #pragma unroll
    for (int t = lane; t < T_; t += 32)
        f_s[w][t] = __ldg(feats + (r * B_ + b) * T_ + t);
    const int kn = g_kn[q];
    const int nl = min(kn, NK);
    for (int i = lane; i < nl; i += 32) {
        int k = g_klist[q * NK + i];
        ki_s[w][i] = k;
        gl_s[w][i] = __ldg(feats + b * K_ + k);
    }
    const float ar  = __ldg(a + r);
    const float G1  = g_G[q * 128 + lane];
    const float G3  = g_G[q * 128 + 32 + lane];
    const float G5  = g_G[q * 128 + 64 + lane];
    const float G7  = g_G[q * 128 + 96 + lane];
    const float Wl  = __ldg(W  + r * HD + lane);
    const float Whl = __ldg(Wh + r * HD + lane);
    const float* wcp = Wc + (r * HD + lane) * K_;
    __syncwarp();

    float keep = 0.f;
    #pragma unroll 1
    for (int g = 0; g < 5; g++) {
        const int tEnd = (g * 32 + 32 < T_) ? g * 32 + 32 : T_;
        #pragma unroll 4
        for (int t = g * 32; t < tEnd; t++) {
            const float f = f_s[w][t];                 // broadcast LDS
            const float x = ar * f;
            const float x2 = x * x, x3 = x2 * x, x5 = x3 * x2, x7 = x5 * x2;
            float hm = x * G1;
            hm = fmaf(T3c * x3, G3, hm);
            hm = fmaf(T5c * x5, G5, hm);
            hm = fmaf(T7c * x7, G7, hm);

            if (kn <= NK) {
                for (int i = 0; i < kn; i++) {         // warp-uniform scan
                    const float y = x * gl_s[w][i];
                    if (fabsf(y) > X0) {               // uniform branch, rare
                        const float y2 = y * y;
                        const float pl = y * fmaf(y2, fmaf(y2, fmaf(y2, T7c, T5c), T3c), 1.0f);
                        const float d  = tanha(y) - pl;
                        hm = fmaf(d, __ldg(wcp + ki_s[w][i]), hm);
                    }
                }
            } else {                                   // overflow fallback (rare)
                for (int k = 0; k < K_; k++) {
                    const float y = x * __ldg(feats + b * K_ + k);
                    if (fabsf(y) > X0) {
                        const float y2 = y * y;
                        const float pl = y * fmaf(y2, fmaf(y2, fmaf(y2, T7c, T5c), T3c), 1.0f);
                        const float d  = tanha(y) - pl;
                        hm = fmaf(d, __ldg(wcp + k), hm);
                    }
                }
            }

            float v = fmaxf(fmaf(f, Wl, hm), 0.0f) * Whl;
            #pragma unroll
            for (int off = 16; off; off >>= 1)
                v += __shfl_xor_sync(0xffffffffu, v, off);
            if (lane == (t & 31)) keep = v + f;
        }
        const int tS = g * 32 + lane;
        if (tS < T_) g_attf[b * K_ + r * T_ + tS] = keep;   // coalesced 32-row store
    }
}

// ---------------- kernel B: MLP 600->128->7 (r10 version, measured 17.7us) ----------------
__global__ __launch_bounds__(512, 1)
void camB(const float* __restrict__ b1,
          const float* __restrict__ W2,
          const float* __restrict__ b2,
          float* __restrict__ out)
{
    __shared__ __align__(16) float v_s[4 * K_];
    __shared__ float part_s[4][4][128];
    __shared__ float h_s[4][128];

    const int bg  = blockIdx.x;
    const int tid = threadIdx.x;

    {
        const float4* src = (const float4*)(g_attf + bg * 4 * K_);
        float4* dst = (float4*)v_s;
        #pragma unroll
        for (int i = tid; i < 4 * K_ / 4; i += 512) dst[i] = src[i];
    }
    __syncthreads();

    const int c  = tid & 127;
    const int kq = tid >> 7;
    const int kbase = kq * 150;

    {
        const float* wp = g_w1t + kbase * 128 + c;
        const float2* vp0 = (const float2*)(v_s + 0 * K_ + kbase);
        const float2* vp1 = (const float2*)(v_s + 1 * K_ + kbase);
        const float2* vp2 = (const float2*)(v_s + 2 * K_ + kbase);
        const float2* vp3 = (const float2*)(v_s + 3 * K_ + kbase);

        float accx[4] = {0.f, 0.f, 0.f, 0.f};
        float accy[4] = {0.f, 0.f, 0.f, 0.f};

        #pragma unroll 5
        for (int it = 0; it < 75; it++) {
            float wx = __ldg(wp + (2 * it) * 128);
            float wy = __ldg(wp + (2 * it + 1) * 128);
            float2 v0 = vp0[it];
            float2 v1 = vp1[it];
            float2 v2 = vp2[it];
            float2 v3 = vp3[it];
            accx[0] = fmaf(wx, v0.x, accx[0]); accy[0] = fmaf(wy, v0.y, accy[0]);
            accx[1] = fmaf(wx, v1.x, accx[1]); accy[1] = fmaf(wy, v1.y, accy[1]);
            accx[2] = fmaf(wx, v2.x, accx[2]); accy[2] = fmaf(wy, v2.y, accy[2]);
            accx[3] = fmaf(wx, v3.x, accx[3]); accy[3] = fmaf(wy, v3.y, accy[3]);
        }
        #pragma unroll
        for (int j = 0; j < 4; j++)
            part_s[kq][j][c] = accx[j] + accy[j];
    }
    __syncthreads();

    {
        const int j = kq;
        h_s[j][c] = part_s[0][j][c] + part_s[1][j][c]
                  + part_s[2][j][c] + part_s[3][j][c] + __ldg(b1 + c);
    }
    __syncthreads();

    if (tid < 28) {
        const int j = tid / 7, o = tid - j * 7;
        float s = __ldg(b2 + o);
        #pragma unroll 8
        for (int cc = 0; cc < 128; cc++)
            s = fmaf(__ldg(W2 + o * 128 + cc), h_s[j][cc], s);
        out[(bg * 4 + j) * 7 + o] = s;
    }
}

// ---------------- launch ----------------
extern "C" void kernel_launch(void* const* d_in, const int* in_sizes, int n_in,
                              void* d_out, int out_size)
{
    const float* feats = (const float*)d_in[0];
    const float* a     = (const float*)d_in[1];
    const float* W     = (const float*)d_in[2];
    const float* Wc    = (const float*)d_in[3];
    const float* Wh    = (const float*)d_in[4];
    const float* W1    = (const float*)d_in[5];
    const float* b1    = (const float*)d_in[6];
    const float* W2    = (const float*)d_in[7];
    const float* b2    = (const float*)d_in[8];
    float* out = (float*)d_out;

    cudaFuncSetAttribute(camG, cudaFuncAttributeMaxDynamicSharedMemorySize, G_SMEM);

    camG<<<dim3(37, 4), 512, G_SMEM>>>(feats, a, Wc, W1);
    camH<<<256, 256>>>(feats, a, W, Wc, Wh);
    camB<<<B_ / 4, 512>>>(b1, W2, b2, out);
}

// round 16
// speedup vs baseline: 25.9485x; 25.9485x over previous
#include <cuda_runtime.h>
#include <cstdint>
#include <math.h>

#define R_   4
#define B_   512
#define T_   150
#define HD   32
#define K_   600
#define NK   64             // per-(r,b) correction-list capacity (kn ~ 3 expected)

// device intermediates
__device__ float g_attf[B_ * K_];
__device__ float g_G[R_ * B_ * 192];          // [q*192 + j*32 + c], powers 1,3,5,7,9,11
__device__ float g_w1t[K_ * 128];             // W1 transposed [k][c]
__device__ int   g_klist[R_ * B_ * NK];
__device__ int   g_kn[R_ * B_];

// ---------------- helpers ----------------
__device__ __forceinline__ float tanha(float x) {
    float y; asm("tanh.approx.f32 %0, %1;" : "=f"(y) : "f"(x)); return y;
}
__device__ __forceinline__ uint32_t packbf(float lo, float hi) {
    uint32_t r; asm("cvt.rn.satfinite.bf16x2.f32 %0, %1, %2;" : "=r"(r) : "f"(hi), "f"(lo)); return r;
}
__device__ __forceinline__ unsigned long long pk2(float lo, float hi) {
    unsigned long long r;
    asm("mov.b64 %0, {%1, %2};" : "=l"(r) : "f"(lo), "f"(hi)); return r;
}
__device__ __forceinline__ void fma2(unsigned long long &acc,
                                     unsigned long long u, unsigned long long w) {
    asm("fma.rn.f32x2 %0, %1, %2, %0;" : "+l"(acc) : "l"(u), "l"(w));
}
__device__ __forceinline__ float2 up2(unsigned long long v) {
    float lo, hi;
    asm("mov.b64 {%0, %1}, %2;" : "=f"(lo), "=f"(hi) : "l"(v));
    return make_float2(lo, hi);
}

// ---------------- kernel G: grid (37,4) = 148 CTAs ----------------
//   x < 32 : G_j GEMM (6 powers), 16 b x 32 c per CTA
//   x 32-35: correction-list pre-pass
//   x == 36: W1 transpose
// dyn smem: wcT[300][33] f32 | gp[16][300] uint4  = 116400 B
#define G_SMEM 116400

__global__ __launch_bounds__(512, 1)
void camG(const float* __restrict__ feats,
          const float* __restrict__ a,
          const float* __restrict__ Wc,
          const float* __restrict__ W1,
          float X0f)
{
    extern __shared__ float sm[];
    const int tid = threadIdx.x;
    const int r   = blockIdx.y;
    const int bx  = blockIdx.x;

    if (bx >= 32) {
        if (bx == 36) {
            for (int i = tid; i < 32 * K_; i += 512) {
                int c_l = i / K_;
                int k   = i - c_l * K_;
                g_w1t[k * 128 + r * 32 + c_l] = __ldg(W1 + (r * 32 + c_l) * K_ + k);
            }
            return;
        }
        const int p = bx - 32;
        const int w = tid >> 5, lane = tid & 31;
        const float ar = fabsf(__ldg(a + r));
        #pragma unroll 1
        for (int i = 0; i < 8; i++) {
            const int b = p * 16 + w + 64 * i;
            float m = 0.f;
            #pragma unroll
            for (int it = 0; it < 5; it++) {
                int t = it * 32 + lane;
                if (t < T_) m = fmaxf(m, fabsf(__ldg(feats + (r * B_ + b) * T_ + t)));
            }
            #pragma unroll
            for (int off = 16; off; off >>= 1)
                m = fmaxf(m, __shfl_xor_sync(0xffffffffu, m, off));
            const float xmax = ar * m;
            float gk[19];
            #pragma unroll
            for (int it = 0; it < 19; it++) {
                int k = it * 32 + lane;
                gk[it] = (k < K_) ? __ldg(feats + b * K_ + k) : 0.f;
            }
            int base = 0;
            #pragma unroll
            for (int it = 0; it < 19; it++) {
                int k = it * 32 + lane;
                bool pq = (k < K_) && (fabsf(gk[it]) * xmax > X0f);
                unsigned mask = __ballot_sync(0xffffffffu, pq);
                int pre = __popc(mask & ((1u << lane) - 1u));
                if (pq && (base + pre) < NK)
                    g_klist[(r * B_ + b) * NK + base + pre] = k;
                base += __popc(mask);
            }
            if (lane == 0) g_kn[r * B_ + b] = base;
        }
        return;
    }

    float* wcT = sm;                          // [300][33]
    uint4* gp  = (uint4*)(sm + 300 * 33);     // [16][300]: {g, g3, bf(g5,g7), bf(g9,g11)}
    const int b0  = bx * 16;
    const int b_l = tid >> 5;
    const int c   = tid & 31;

    unsigned long long A13 = 0ull, A57 = 0ull, A911 = 0ull;

    for (int kc = 0; kc < K_; kc += 300) {
        __syncthreads();
        for (int i = tid; i < 32 * 300; i += 512) {
            int cc = i / 300, kk = i - cc * 300;
            wcT[kk * 33 + cc] = __ldg(Wc + (r * HD + cc) * K_ + kc + kk);
        }
        for (int i = tid; i < 16 * 300; i += 512) {
            int bb = i / 300, kk = i - bb * 300;
            float g  = __ldg(feats + (b0 + bb) * K_ + kc + kk);
            float g2 = g * g;
            float g3 = g2 * g, g4 = g2 * g2;
            float g5 = g4 * g, g7 = g5 * g2, g9 = g7 * g2, g11 = g9 * g2;
            gp[bb * 300 + kk] = make_uint4(__float_as_uint(g), __float_as_uint(g3),
                                           packbf(g5, g7), packbf(g9, g11));
        }
        __syncthreads();
        #pragma unroll 4
        for (int kk = 0; kk < 300; kk++) {
            uint4 gv = gp[b_l * 300 + kk];                 // broadcast LDS.128
            float wc = wcT[kk * 33 + c];
            unsigned long long wc2 = pk2(wc, wc);
            float g   = __uint_as_float(gv.x);
            float g3  = __uint_as_float(gv.y);
            float g5  = __uint_as_float(gv.z << 16);
            float g7  = __uint_as_float(gv.z & 0xFFFF0000u);
            float g9  = __uint_as_float(gv.w << 16);
            float g11 = __uint_as_float(gv.w & 0xFFFF0000u);
            fma2(A13,  pk2(g,  g3),  wc2);
            fma2(A57,  pk2(g5, g7),  wc2);
            fma2(A911, pk2(g9, g11), wc2);
        }
    }
    float2 s13 = up2(A13), s57 = up2(A57), s911 = up2(A911);
    int base = ((r * B_) + b0 + b_l) * 192 + c;
    g_G[base]       = s13.x;
    g_G[base + 32]  = s13.y;
    g_G[base + 64]  = s57.x;
    g_G[base + 96]  = s57.y;
    g_G[base + 128] = s911.x;
    g_G[base + 160] = s911.y;
}

// ---------------- kernel H: warp-per-(r,b), tiled phases ----------------
// grid 256, block 256 (8 warps/CTA; 2048 warps)
__global__ __launch_bounds__(256, 2)
void camH(const float* __restrict__ feats,
          const float* __restrict__ a,
          const float* __restrict__ W,
          const float* __restrict__ Wc,
          const float* __restrict__ Wh,
          float C1, float C3, float C5, float C7, float C9, float C11,
          float invA, float Af, float X0f)
{
    __shared__ float f_s[8][160];
    __shared__ float hm_s[8][32][33];
    __shared__ float gl_s[8][NK];
    __shared__ int   ki_s[8][NK];
    __shared__ float W_s[8][32], Wh_s[8][32];

    const int tid  = threadIdx.x;
    const int w    = tid >> 5;
    const int lane = tid & 31;
    const int q    = blockIdx.x * 8 + w;
    const int r    = q >> 9;
    const int b    = q & 511;

    // warp staging
    #pragma unroll
    for (int t = lane; t < T_; t += 32)
        f_s[w][t] = __ldg(feats + (r * B_ + b) * T_ + t);
    const int kn = g_kn[q];
    const int nl = min(kn, NK);
    for (int i = lane; i < nl; i += 32) {
        int k = g_klist[q * NK + i];
        ki_s[w][i] = k;
        gl_s[w][i] = __ldg(feats + b * K_ + k);
    }
    W_s[w][lane]  = __ldg(W  + r * HD + lane);
    Wh_s[w][lane] = __ldg(Wh + r * HD + lane);
    const float arA = __ldg(a + r) * invA;     // x/A = (a*f)/A
    const float cg1  = C1  * g_G[q * 192 + lane];
    const float cg3  = C3  * g_G[q * 192 + 32  + lane];
    const float cg5  = C5  * g_G[q * 192 + 64  + lane];
    const float cg7  = C7  * g_G[q * 192 + 96  + lane];
    const float cg9  = C9  * g_G[q * 192 + 128 + lane];
    const float cg11 = C11 * g_G[q * 192 + 160 + lane];
    __syncwarp();

    #pragma unroll 1
    for (int tile = 0; tile < 5; tile++) {
        const int tb  = tile * 32;
        const int cnt = (tb + 32 <= T_) ? 32 : (T_ - tb);

        // Phase A (lane = c): poly Horner, G in registers
        #pragma unroll 4
        for (int tt = 0; tt < cnt; tt++) {
            const float f  = f_s[w][tb + tt];          // broadcast
            const float xs = arA * f;
            const float s  = xs * xs;
            float h = cg11;
            h = fmaf(h, s, cg9);
            h = fmaf(h, s, cg7);
            h = fmaf(h, s, cg5);
            h = fmaf(h, s, cg3);
            h = fmaf(h, s, cg1);
            hm_s[w][tt][lane] = h * xs;
        }
        __syncwarp();

        // Phase B (lane = t): rare exact corrections
        if (lane < cnt) {
            const float f  = f_s[w][tb + lane];
            const float xs = arA * f;
            const int nIter = (kn <= NK) ? kn : K_;
            for (int i = 0; i < nIter; i++) {
                int   k;
                float g;
                if (kn <= NK) { k = ki_s[w][i]; g = gl_s[w][i]; }
                else          { k = i; g = __ldg(feats + b * K_ + k); }
                const float u = xs * g;
                const float y = u * Af;
                if (fabsf(y) > X0f) {
                    const float uu = u * u;
                    float pl = C11;
                    pl = fmaf(pl, uu, C9);
                    pl = fmaf(pl, uu, C7);
                    pl = fmaf(pl, uu, C5);
                    pl = fmaf(pl, uu, C3);
                    pl = fmaf(pl, uu, C1);
                    const float d = tanha(y) - pl * u;
                    const float* wcp = Wc + r * HD * K_ + k;
                    #pragma unroll 8
                    for (int c = 0; c < 32; c++)
                        hm_s[w][lane][c] += d * __ldg(wcp + c * K_);
                }
            }
        }
        __syncwarp();

        // Phase C (lane = t): relu + Wh reduction + store
        if (lane < cnt) {
            const float f = f_s[w][tb + lane];
            float v = f;
            #pragma unroll 8
            for (int c = 0; c < 32; c++) {
                float hv = fmaf(f, W_s[w][c], hm_s[w][lane][c]);
                v = fmaf(fmaxf(hv, 0.f), Wh_s[w][c], v);
            }
            g_attf[b * K_ + r * T_ + tb + lane] = v;
        }
        __syncwarp();
    }
}

// ---------------- kernel B: MLP 600->128->7 (r10 version, measured 17.7us) ----------------
__global__ __launch_bounds__(512, 1)
void camB(const float* __restrict__ b1,
          const float* __restrict__ W2,
          const float* __restrict__ b2,
          float* __restrict__ out)
{
    __shared__ __align__(16) float v_s[4 * K_];
    __shared__ float part_s[4][4][128];
    __shared__ float h_s[4][128];

    const int bg  = blockIdx.x;
    const int tid = threadIdx.x;

    {
        const float4* src = (const float4*)(g_attf + bg * 4 * K_);
        float4* dst = (float4*)v_s;
        #pragma unroll
        for (int i = tid; i < 4 * K_ / 4; i += 512) dst[i] = src[i];
    }
    __syncthreads();

    const int c  = tid & 127;
    const int kq = tid >> 7;
    const int kbase = kq * 150;

    {
        const float* wp = g_w1t + kbase * 128 + c;
        const float2* vp0 = (const float2*)(v_s + 0 * K_ + kbase);
        const float2* vp1 = (const float2*)(v_s + 1 * K_ + kbase);
        const float2* vp2 = (const float2*)(v_s + 2 * K_ + kbase);
        const float2* vp3 = (const float2*)(v_s + 3 * K_ + kbase);

        float accx[4] = {0.f, 0.f, 0.f, 0.f};
        float accy[4] = {0.f, 0.f, 0.f, 0.f};

        #pragma unroll 5
        for (int it = 0; it < 75; it++) {
            float wx = __ldg(wp + (2 * it) * 128);
            float wy = __ldg(wp + (2 * it + 1) * 128);
            float2 v0 = vp0[it];
            float2 v1 = vp1[it];
            float2 v2 = vp2[it];
            float2 v3 = vp3[it];
            accx[0] = fmaf(wx, v0.x, accx[0]); accy[0] = fmaf(wy, v0.y, accy[0]);
            accx[1] = fmaf(wx, v1.x, accx[1]); accy[1] = fmaf(wy, v1.y, accy[1]);
            accx[2] = fmaf(wx, v2.x, accx[2]); accy[2] = fmaf(wy, v2.y, accy[2]);
            accx[3] = fmaf(wx, v3.x, accx[3]); accy[3] = fmaf(wy, v3.y, accy[3]);
        }
        #pragma unroll
        for (int j = 0; j < 4; j++)
            part_s[kq][j][c] = accx[j] + accy[j];
    }
    __syncthreads();

    {
        const int j = kq;
        h_s[j][c] = part_s[0][j][c] + part_s[1][j][c]
                  + part_s[2][j][c] + part_s[3][j][c] + __ldg(b1 + c);
    }
    __syncthreads();

    if (tid < 28) {
        const int j = tid / 7, o = tid - j * 7;
        float s = __ldg(b2 + o);
        #pragma unroll 8
        for (int cc = 0; cc < 128; cc++)
            s = fmaf(__ldg(W2 + o * 128 + cc), h_s[j][cc], s);
        out[(bg * 4 + j) * 7 + o] = s;
    }
}

// ---------------- launch ----------------
extern "C" void kernel_launch(void* const* d_in, const int* in_sizes, int n_in,
                              void* d_out, int out_size)
{
    const float* feats = (const float*)d_in[0];
    const float* a     = (const float*)d_in[1];
    const float* W     = (const float*)d_in[2];
    const float* Wc    = (const float*)d_in[3];
    const float* Wh    = (const float*)d_in[4];
    const float* W1    = (const float*)d_in[5];
    const float* b1    = (const float*)d_in[6];
    const float* W2    = (const float*)d_in[7];
    const float* b2    = (const float*)d_in[8];
    float* out = (float*)d_out;

    // host-side Chebyshev fit of tanh on [-A, A], odd degree 13 -> monomials in u=y/A
    const double A  = 1.8;
    const double X0 = 1.7;
    const double PI = 3.14159265358979323846;
    const int N = 64;
    double aa[13] = {0};
    for (int n = 1; n <= 11; n += 2) {
        double s = 0;
        for (int i = 0; i < N; i++) {
            double th = PI * (i + 0.5) / N;
            s += tanh(A * cos(th)) * cos(n * th);
        }
        aa[n] = 2.0 * s / N;
    }
    double a1 = aa[1], a3 = aa[3], a5 = aa[5], a7 = aa[7], a9 = aa[9], a11 = aa[11];
    float c1  = (float)(a1 - 3*a3 + 5*a5 - 7*a7 + 9*a9 - 11*a11);
    float c3  = (float)(4*a3 - 20*a5 + 56*a7 - 120*a9 + 220*a11);
    float c5  = (float)(16*a5 - 112*a7 + 432*a9 - 1232*a11);
    float c7  = (float)(64*a7 - 576*a9 + 2816*a11);
    float c9  = (float)(256*a9 - 2816*a11);
    float c11 = (float)(1024*a11);

    cudaFuncSetAttribute(camG, cudaFuncAttributeMaxDynamicSharedMemorySize, G_SMEM);

    camG<<<dim3(37, 4), 512, G_SMEM>>>(feats, a, Wc, W1, (float)X0);
    camH<<<256, 256>>>(feats, a, W, Wc, Wh,
                       c1, c3, c5, c7, c9, c11,
                       (float)(1.0 / A), (float)A, (float)X0);
    camB<<<B_ / 4, 512>>>(b1, W2, b2, out);
}